// round 9
// baseline (speedup 1.0000x reference)
#include <cuda_runtime.h>
#include <cuda_fp16.h>
#include <cstdint>

#define BS    8
#define CDIM  256
#define SP    16384            // 16*32*32 spatial per batch
#define NTOK  (BS * SP)        // 131072
#define NCODE 1024
#define NQ    (BS * CDIM * SP) // 33554432

#define MT     64              // tokens per screen block
#define ZPB    272             // padded int8 row stride (bytes, 16-aligned, 4-bank shift)
#define SCODES 64              // codes per stage
#define NSTAGE (NCODE / SCODES) // 16
#define MAXCAND 16
#define ECQ    3.8447e-6f      // codebook quant err: 0.5/(127*1024)
#define CSCALE 130048.0f       // 127*1024

__device__ float g_cnorm[NCODE];
__device__ float g_cl1[NCODE];
__device__ unsigned int g_cl1max;        // fenc-encoded max L1(c)
__device__ int   g_idx[NTOK];
__device__ __align__(16) char g_cbi[NCODE * CDIM];  // int8 codebook [code][k]

// ---------------- PTX helpers (sm_103-safe, no 'a' features) ---------------
#define CP_ASYNC16(dst, src) asm volatile("cp.async.cg.shared.global [%0], [%1], 16;" :: "r"(dst), "l"(src) : "memory")
#define CP_COMMIT()          asm volatile("cp.async.commit_group;" ::: "memory")
#define CP_WAIT0()           asm volatile("cp.async.wait_group 0;" ::: "memory")

__device__ __forceinline__ uint32_t smem_u32(const void* p) {
    uint32_t a;
    asm("{ .reg .u64 t; cvta.to.shared.u64 t, %1; cvt.u32.u64 %0, t; }" : "=r"(a) : "l"(p));
    return a;
}
__device__ __forceinline__ void mma16832s8(int4& c, const uint32_t* a, const uint32_t* b) {
    asm volatile("mma.sync.aligned.m16n8k32.row.col.s32.s8.s8.s32 "
        "{%0,%1,%2,%3}, {%4,%5,%6,%7}, {%8,%9}, {%0,%1,%2,%3};"
        : "+r"(c.x), "+r"(c.y), "+r"(c.z), "+r"(c.w)
        : "r"(a[0]), "r"(a[1]), "r"(a[2]), "r"(a[3]), "r"(b[0]), "r"(b[1]));
}
// order-preserving float<->uint for atomicMin/Max
__device__ __forceinline__ uint32_t fenc(float f) {
    uint32_t u = __float_as_uint(f);
    return (u >> 31) ? ~u : (u | 0x80000000u);
}
__device__ __forceinline__ float fdec(uint32_t k) {
    uint32_t u = (k >> 31) ? (k & 0x7fffffffu) : ~k;
    return __uint_as_float(u);
}
__device__ __forceinline__ void ins5(float v, int j, float* bv, int* bi) {
    if (v < bv[4]) {
        bv[4] = v; bi[4] = j;
#pragma unroll
        for (int q = 3; q >= 0; --q) {
            if (bv[q + 1] < bv[q]) {
                float tv = bv[q]; bv[q] = bv[q + 1]; bv[q + 1] = tv;
                int   ti = bi[q]; bi[q] = bi[q + 1]; bi[q + 1] = ti;
            }
        }
    }
}

// ---------------------------------------------------------------------------
// per-code: exact ||c||^2 (bit-exact recipe), L1(c), global max L1
// ---------------------------------------------------------------------------
__global__ void cnorm_kernel(const float* __restrict__ cb) {
    int r = blockIdx.x * 256 + threadIdx.x;
    const float* row = cb + (size_t)r * CDIM;
    float s = 0.f, l1 = 0.f;
#pragma unroll 8
    for (int k = 0; k < CDIM; ++k) {
        float v = row[k];
        s = __fadd_rn(s, __fmul_rn(v, v));
        l1 += fabsf(v);
    }
    g_cnorm[r] = s;
    g_cl1[r] = l1;
    atomicMax(&g_cl1max, fenc(l1));
}

// int8 codebook quantization
__global__ void cbi_kernel(const float* __restrict__ cb) {
    int i = blockIdx.x * 256 + threadIdx.x;
    int q = __float2int_rn(cb[i] * CSCALE);
    q = max(-127, min(127, q));
    g_cbi[i] = (char)q;
}

// ---------------------------------------------------------------------------
// IMMA screening + margin candidates + bit-exact rescore.
// 256 thr = 8 warps = 4 token-groups (16 tok) x 2 code-halves (32 codes/stage).
// Per warp/stage: m16 x n32, K=256 (8 k32-steps) = 32 IMMA. 2 CTAs/SM.
// ---------------------------------------------------------------------------
#define CBST_B   (SCODES * ZPB)                    // 17408
#define SM_ZT    0                                 // [64][272] int8
#define SM_CB    (MT * ZPB)                        // 17408
#define SM_CNS   (SM_CB + 2 * CBST_B)              // 52224
#define SM_CL1   (SM_CNS + NCODE * 4)              // 56320
#define SM_MAXP  (SM_CL1 + NCODE * 4)              // 60416 : [4][64] maxabs partials
#define SM_L1P   (SM_MAXP + 4 * MT * 4)            // 61440 : [4][64] L1 partials
#define SM_FCT   (SM_L1P + 4 * MT * 4)             // 62464 : per-token recon factor
#define SM_EZN   (SM_FCT + MT * 4)                 // 62720 : per-token quant err
#define SM_L1Z   (SM_EZN + MT * 4)                 // 62976
#define SM_RCP   (SM_L1Z + MT * 4)                 // 63232 : per-token 1/step
#define SM_MINK  (SM_RCP + MT * 4)                 // 63488
#define SM_CCNT  (SM_MINK + MT * 4)                // 63744
#define SM_CAND  (SM_CCNT + MT * 4)                // 64000
#define SM_TOTAL (SM_CAND + MT * MAXCAND * 4)      // 68096

__global__ __launch_bounds__(256, 2)
void screen_kernel(const float* __restrict__ z, const float* __restrict__ cb,
                   float* __restrict__ oidx)
{
    extern __shared__ char smem[];
    char*  zi8 = smem + SM_ZT;
    float* cns = (float*)(smem + SM_CNS);
    float* cl1 = (float*)(smem + SM_CL1);
    float* maxp = (float*)(smem + SM_MAXP);
    float* l1p  = (float*)(smem + SM_L1P);
    float* fct  = (float*)(smem + SM_FCT);
    float* ezn  = (float*)(smem + SM_EZN);
    float* l1z  = (float*)(smem + SM_L1Z);
    float* rcp  = (float*)(smem + SM_RCP);
    uint32_t* minkey = (uint32_t*)(smem + SM_MINK);
    int* candcnt = (int*)(smem + SM_CCNT);
    int* cand    = (int*)(smem + SM_CAND);

    const int tid = threadIdx.x;
    const int wid = tid >> 5, lane = tid & 31;
    const int tg = wid >> 1, ch = wid & 1;
    const int r = lane >> 2, c4 = (lane & 3) * 4, c2 = (lane & 3) * 2;

    const int n0 = blockIdx.x * MT;
    const int b  = n0 / SP, s0 = n0 % SP;
    const float* zbase = z + (size_t)b * CDIM * SP + s0;

    uint32_t cbu0 = smem_u32(smem + SM_CB);
    uint32_t cbu1 = cbu0 + CBST_B;

    const float cl1maxv = fdec(g_cl1max);

    // ---- prologue A: per-token maxabs + L1 partials; cns/cl1; stage-0 cp ----
    {
        const int tok = tid & 63, grp = tid >> 6;   // 4 threads per token
        float mx = 0.f, l1 = 0.f;
        for (int k = grp; k < CDIM; k += 4) {
            float v = fabsf(zbase[(size_t)k * SP + tok]);
            mx = fmaxf(mx, v); l1 += v;
        }
        maxp[grp * MT + tok] = mx;
        l1p[grp * MT + tok] = l1;
    }
    for (int i = tid; i < NCODE; i += 256) { cns[i] = g_cnorm[i]; cl1[i] = g_cl1[i]; }
    if (tid < MT) { minkey[tid] = 0xFFFFFFFFu; candcnt[tid] = 0; }
    {
        const char* src = g_cbi;                   // stage 0: 64 codes x 256 B
#pragma unroll
        for (int it = 0; it < 4; ++it) {
            int id = tid + it * 256;
            int cc = id >> 4, kc = (id & 15) * 16;
            CP_ASYNC16(cbu0 + (uint32_t)(cc * ZPB + kc), src + cc * CDIM + kc);
        }
        CP_COMMIT();
    }
    __syncthreads();

    // ---- prologue B: per-token scale; quantize z tile ----
    if (tid < MT) {
        float mx = fmaxf(fmaxf(maxp[tid], maxp[MT + tid]),
                         fmaxf(maxp[2 * MT + tid], maxp[3 * MT + tid]));
        float l1 = l1p[tid] + l1p[MT + tid] + l1p[2 * MT + tid] + l1p[3 * MT + tid];
        float step = fmaxf(mx, 1e-30f) * (1.0f / 127.0f);
        rcp[tid] = 1.0f / step;
        fct[tid] = step * (2.0f / CSCALE);
        ezn[tid] = step * 0.5f;
        l1z[tid] = l1;
    }
    __syncthreads();
    {
        const int tok = tid & 63, grp = tid >> 6;
        float rc = rcp[tok];
        for (int k = grp; k < CDIM; k += 4) {
            int q = __float2int_rn(zbase[(size_t)k * SP + tok] * rc);
            q = max(-127, min(127, q));
            zi8[tok * ZPB + k] = (char)q;
        }
    }
    CP_WAIT0();
    __syncthreads();

    // per-thread token-slot constants (slot0: row tg*16+r, slot1: +8)
    const int tok0 = tg * 16 + r, tok1 = tok0 + 8;
    const float f0 = fct[tok0], f1 = fct[tok1];

    float bv[2][5]; int bi[2][5];
#pragma unroll
    for (int s = 0; s < 2; ++s)
#pragma unroll
        for (int q = 0; q < 5; ++q) { bv[s][q] = 3.4e38f; bi[s][q] = 0; }

    for (int st = 0; st < NSTAGE; ++st) {
        if (st + 1 < NSTAGE) {
            const char* src = g_cbi + (size_t)(st + 1) * SCODES * CDIM;
            uint32_t dstb = ((st + 1) & 1) ? cbu1 : cbu0;
#pragma unroll
            for (int it = 0; it < 4; ++it) {
                int id = tid + it * 256;
                int cc = id >> 4, kc = (id & 15) * 16;
                CP_ASYNC16(dstb + (uint32_t)(cc * ZPB + kc), src + cc * CDIM + kc);
            }
            CP_COMMIT();
        }

        // ---- compute stage st ----
        const char* zw = zi8 + (tg * 16) * ZPB;
        const char* bw = smem + SM_CB + (st & 1) * CBST_B + (ch * 32) * ZPB;

        int4 acc[4];
#pragma unroll
        for (int nj = 0; nj < 4; ++nj) acc[nj] = make_int4(0, 0, 0, 0);

#pragma unroll
        for (int ks = 0; ks < 8; ++ks) {
            int kb = ks * 32;
            uint32_t A[4], B[4][2];
            const char* zr0 = zw + r * ZPB + kb + c4;
            const char* zr1 = zw + (r + 8) * ZPB + kb + c4;
            A[0] = *(const uint32_t*)(zr0);
            A[1] = *(const uint32_t*)(zr1);
            A[2] = *(const uint32_t*)(zr0 + 16);
            A[3] = *(const uint32_t*)(zr1 + 16);
#pragma unroll
            for (int nj = 0; nj < 4; ++nj) {
                const char* br = bw + (nj * 8 + r) * ZPB + kb + c4;
                B[nj][0] = *(const uint32_t*)(br);
                B[nj][1] = *(const uint32_t*)(br + 16);
            }
#pragma unroll
            for (int nj = 0; nj < 4; ++nj)
                mma16832s8(acc[nj], A, B[nj]);
        }

        // ---- epilogue: scores + per-thread top-5 per token slot ----
        int jbase = st * SCODES + ch * 32 + c2;
#pragma unroll
        for (int nj = 0; nj < 4; ++nj) {
            int j = jbase + nj * 8;
            float cn0 = cns[j], cn1 = cns[j + 1];
            ins5(cn0 - f0 * (float)acc[nj].x, j,     bv[0], bi[0]);
            ins5(cn1 - f0 * (float)acc[nj].y, j + 1, bv[0], bi[0]);
            ins5(cn0 - f1 * (float)acc[nj].z, j,     bv[1], bi[1]);
            ins5(cn1 - f1 * (float)acc[nj].w, j + 1, bv[1], bi[1]);
        }

        CP_WAIT0();
        __syncthreads();
    }

    // ---- per-token screened min ----
    atomicMin(&minkey[tok0], fenc(bv[0][0]));
    atomicMin(&minkey[tok1], fenc(bv[1][0]));
    __syncthreads();

    // ---- append candidates within deterministic margin ----
#pragma unroll
    for (int s = 0; s < 2; ++s) {
        int tokl = s ? tok1 : tok0;
        float ez = ezn[tokl];
        float thrbase = fdec(minkey[tokl]) + 4.0f * ECQ * l1z[tokl]
                      + 4.0f * 256.0f * ez * ECQ + 1e-7f;
#pragma unroll
        for (int q = 0; q < 5; ++q) {
            float thr = thrbase + 2.0f * ez * (cl1[bi[s][q]] + cl1maxv);
            if (bv[s][q] <= thr) {
                int pos = atomicAdd(&candcnt[tokl], 1);
                if (pos < MAXCAND) cand[tokl * MAXCAND + pos] = bi[s][q];
            }
        }
    }
    __syncthreads();

    // ---- resolve: exact rescore (bit-exact XLA:CPU recipe) when ambiguous ----
    if (tid < MT) {
        int tok = tid;
        int cnt = candcnt[tok]; if (cnt > MAXCAND) cnt = MAXCAND;
        int best = cand[tok * MAXCAND];
        if (cnt > 1) {
            const float* zp = zbase + tok;
            float zn = 0.f;
#pragma unroll 8
            for (int k = 0; k < CDIM; ++k) {
                float v = zp[(size_t)k * SP];
                zn = __fadd_rn(zn, __fmul_rn(v, v));
            }
            float bsc = 3.4e38f; best = 0x7fffffff;
            for (int q = 0; q < cnt; ++q) {
                int j = cand[tok * MAXCAND + q];
                const float* cr = cb + (size_t)j * CDIM;
                float acc = 0.f;
#pragma unroll 8
                for (int k = 0; k < CDIM; ++k)
                    acc = __fmaf_rn(zp[(size_t)k * SP], cr[k], acc);
                float sc = __fadd_rn(__fadd_rn(zn, __fmul_rn(acc, -2.f)), cns[j]);
                if (sc < bsc || (sc == bsc && j < best)) { bsc = sc; best = j; }
            }
        }
        int n = n0 + tok;
        g_idx[n] = best;
        if (oidx) oidx[n] = (float)best;
    }
}

// ---------------------------------------------------------------------------
// gather + transpose writer: 32 tokens x 256 ch per block
// ---------------------------------------------------------------------------
#define WT 32
#define WP 33
__global__ __launch_bounds__(256) void write_kernel(
    const float* __restrict__ cb, const float* __restrict__ z,
    float* __restrict__ outq, float* __restrict__ outst)
{
    __shared__ float tile[CDIM * WP];
    __shared__ int   sidx[WT];

    const int tid = threadIdx.x;
    const int n0  = blockIdx.x * WT;
    const int b   = n0 / SP, s0 = n0 % SP;

    if (tid < WT) sidx[tid] = g_idx[n0 + tid];
    __syncthreads();

    const int c = tid;
#pragma unroll 8
    for (int tok = 0; tok < WT; ++tok)
        tile[c * WP + tok] = cb[(size_t)sidx[tok] * CDIM + c];
    __syncthreads();

    const size_t base = (size_t)b * CDIM * SP + s0;
#pragma unroll 4
    for (int rr = 0; rr < WT; ++rr) {
        int lin = rr * 256 + tid;
        int cc = lin >> 5, tok = lin & 31;
        size_t addr = base + (size_t)cc * SP + tok;
        float q = tile[cc * WP + tok];
        outq[addr] = q;
        if (outst) {
            float zv = z[addr];
            outst[addr] = __fadd_rn(zv, __fadd_rn(q, -zv));
        }
    }
}

// ---------------------------------------------------------------------------
extern "C" void kernel_launch(void* const* d_in, const int* in_sizes, int n_in,
                              void* d_out, int out_size) {
    const float* z  = (const float*)d_in[0];
    const float* cb = (const float*)d_in[1];
    float* out = (float*)d_out;

    float* outq   = out;
    float* outst  = nullptr;
    float* outidx = nullptr;
    if (out_size >= 2 * NQ + NTOK)      { outst = out + NQ; outidx = out + 2 * (size_t)NQ; }
    else if (out_size >= 2 * NQ)        { outst = out + NQ; }
    else if (out_size >= NQ + NTOK)     { outidx = out + NQ; }

    cudaFuncSetAttribute(screen_kernel, cudaFuncAttributeMaxDynamicSharedMemorySize, SM_TOTAL);

    cnorm_kernel<<<NCODE / 256, 256>>>(cb);
    cbi_kernel<<<NCODE * CDIM / 256, 256>>>(cb);
    screen_kernel<<<NTOK / MT, 256, SM_TOTAL>>>(z, cb, outidx);
    write_kernel<<<NTOK / WT, 256>>>(cb, z, outq, outst);
}

// round 12
// speedup vs baseline: 1.9716x; 1.9716x over previous
#include <cuda_runtime.h>
#include <cuda_fp16.h>
#include <cstdint>

#define BS    8
#define CDIM  256
#define SP    16384            // 16*32*32 spatial per batch
#define NTOK  (BS * SP)        // 131072
#define NCODE 1024
#define NQ    (BS * CDIM * SP) // 33554432

#define MT     64              // tokens per screen block
#define ZP     264             // padded smem row stride (halves); 528B = 4-bank row shift
#define SCODES 64              // codes per stage
#define NSTAGE (NCODE / SCODES) // 16
#define MARGIN 1.5e-3f
#define MAXCAND 12

__device__ float  g_cnorm[NCODE];
__device__ int    g_idx[NTOK];
__device__ __half g_cbh[NCODE * CDIM];   // fp16 codebook, plain [code][k]

// ---------------- PTX helpers (sm_103-safe, no 'a' features) ---------------
#define CP_ASYNC16(dst, src) asm volatile("cp.async.cg.shared.global [%0], [%1], 16;" :: "r"(dst), "l"(src) : "memory")
#define CP_COMMIT()          asm volatile("cp.async.commit_group;" ::: "memory")
#define CP_WAIT0()           asm volatile("cp.async.wait_group 0;" ::: "memory")

__device__ __forceinline__ uint32_t smem_u32(const void* p) {
    uint32_t a;
    asm("{ .reg .u64 t; cvta.to.shared.u64 t, %1; cvt.u32.u64 %0, t; }" : "=r"(a) : "l"(p));
    return a;
}
#define LDMX4(r0, r1, r2, r3, addr) \
    asm volatile("ldmatrix.sync.aligned.m8n8.x4.shared.b16 {%0,%1,%2,%3}, [%4];" \
        : "=r"(r0), "=r"(r1), "=r"(r2), "=r"(r3) : "r"(addr))

__device__ __forceinline__ void mma16816(float4& c, const uint32_t* a, const uint32_t* b) {
    asm volatile("mma.sync.aligned.m16n8k16.row.col.f32.f16.f16.f32 "
        "{%0,%1,%2,%3}, {%4,%5,%6,%7}, {%8,%9}, {%0,%1,%2,%3};"
        : "+f"(c.x), "+f"(c.y), "+f"(c.z), "+f"(c.w)
        : "r"(a[0]), "r"(a[1]), "r"(a[2]), "r"(a[3]), "r"(b[0]), "r"(b[1]));
}
// order-preserving float<->uint for atomicMin
__device__ __forceinline__ uint32_t fenc(float f) {
    uint32_t u = __float_as_uint(f);
    return (u >> 31) ? ~u : (u | 0x80000000u);
}
__device__ __forceinline__ float fdec(uint32_t k) {
    uint32_t u = (k >> 31) ? (k & 0x7fffffffu) : ~k;
    return __uint_as_float(u);
}
__device__ __forceinline__ void ins5(float v, int j, float* bv, int* bi) {
    if (v < bv[4]) {
        bv[4] = v; bi[4] = j;
#pragma unroll
        for (int q = 3; q >= 0; --q) {
            if (bv[q + 1] < bv[q]) {
                float tv = bv[q]; bv[q] = bv[q + 1]; bv[q + 1] = tv;
                int   ti = bi[q]; bi[q] = bi[q + 1]; bi[q + 1] = ti;
            }
        }
    }
}

// ---------------------------------------------------------------------------
// ||c_j||^2 exact (scalar sequential ascending k — validated bit-exact)
// ---------------------------------------------------------------------------
__global__ void cnorm_kernel(const float* __restrict__ cb) {
    int r = blockIdx.x * 256 + threadIdx.x;
    const float* row = cb + (size_t)r * CDIM;
    float s = 0.f;
#pragma unroll 8
    for (int k = 0; k < CDIM; ++k) { float v = row[k]; s = __fadd_rn(s, __fmul_rn(v, v)); }
    g_cnorm[r] = s;
}

// fp16 codebook conversion (plain layout)
__global__ void cbh_kernel(const float* __restrict__ cb) {
    int i = blockIdx.x * 256 + threadIdx.x;
    g_cbh[i] = __float2half_rn(cb[i]);
}

// ---------------------------------------------------------------------------
// HMMA screening via ldmatrix, 2 CTAs/SM, + margin candidates + exact rescore.
// 256 thr = 8 warps = 4 token-groups (16 tok) x 2 code-halves (32 codes/stage).
// Per warp/stage: m16 x n32, K=256 -> 16 ksteps x (1 A-ldmx4 + 2 B-ldmx4 + 4 mma)
// ---------------------------------------------------------------------------
#define CB_BYTES (SCODES * ZP * 2)                 // 33792
#define SM_ZT    0                                 // [64][264] half = 33792
#define SM_CB    (MT * ZP * 2)                     // 33792
#define SM_CNS   (SM_CB + 2 * CB_BYTES)            // 101376
#define SM_MINK  (SM_CNS + NCODE * 4)              // 105472
#define SM_CCNT  (SM_MINK + MT * 4)                // 105728
#define SM_CAND  (SM_CCNT + MT * 4)                // 105984
#define SM_TOTAL (SM_CAND + MT * MAXCAND * 4)      // 109056

__global__ __launch_bounds__(256, 2)
void screen_kernel(const float* __restrict__ z, const float* __restrict__ cb,
                   float* __restrict__ oidx)
{
    extern __shared__ char smem[];
    __half* zt = (__half*)(smem + SM_ZT);
    float*  cns = (float*)(smem + SM_CNS);
    uint32_t* minkey = (uint32_t*)(smem + SM_MINK);
    int* candcnt = (int*)(smem + SM_CCNT);
    int* cand    = (int*)(smem + SM_CAND);

    const int tid = threadIdx.x;
    const int wid = tid >> 5, lane = tid & 31;
    const int tg = wid >> 1, ch = wid & 1;        // token group (16 tok) / code half
    const int r = lane >> 2, c2 = (lane & 3) * 2;

    const int n0 = blockIdx.x * MT;
    const int b  = n0 / SP, s0 = n0 % SP;
    const float* zbase = z + (size_t)b * CDIM * SP + s0;

    uint32_t cbu0 = smem_u32(smem + SM_CB);
    uint32_t cbu1 = cbu0 + CB_BYTES;

    // ldmatrix per-lane addresses (bytes):
    //  A (m16k16, row-major): row = lane&15, +16B for lanes>=16 (k 8..15)
    const uint32_t a_lane_off = (uint32_t)((lane & 15) * (ZP * 2) + (lane >> 4) * 16);
    //  B (two n8k16 from [code][k]): code = (lane&7) + ((lane>>4)&1)*8 ; +16B if bit3
    const uint32_t b_lane_off = (uint32_t)((((lane & 7) + ((lane >> 4) & 1) * 8)) * (ZP * 2)
                                           + ((lane >> 3) & 1) * 16);

    // ---- prologue: z tile fp16 (padded), cns, mins, stage-0 cp.async ----
    for (int i = tid; i < MT * CDIM; i += 256) {
        int tok = i & 63, k = i >> 6;
        zt[tok * ZP + k] = __float2half_rn(zbase[(size_t)k * SP + tok]);
    }
    for (int i = tid; i < NCODE; i += 256) cns[i] = g_cnorm[i];
    if (tid < MT) { minkey[tid] = 0xFFFFFFFFu; candcnt[tid] = 0; }
    {
        const __half* src = g_cbh;     // stage 0: 64 codes x 256 halves
#pragma unroll
        for (int it = 0; it < 8; ++it) {
            int id = tid + it * 256;
            int cc = id >> 5, kc = (id & 31) * 8;
            CP_ASYNC16(cbu0 + (uint32_t)(cc * ZP + kc) * 2, src + cc * CDIM + kc);
        }
        CP_COMMIT();
    }
    CP_WAIT0();
    __syncthreads();

    const uint32_t za = smem_u32(zt + (tg * 16) * ZP) + a_lane_off;

    float bv[2][5]; int bi[2][5];
#pragma unroll
    for (int s = 0; s < 2; ++s)
#pragma unroll
        for (int q = 0; q < 5; ++q) { bv[s][q] = 3.4e38f; bi[s][q] = 0; }

    for (int st = 0; st < NSTAGE; ++st) {
        // issue next stage loads into the other buffer
        if (st + 1 < NSTAGE) {
            const __half* src = g_cbh + (size_t)(st + 1) * SCODES * CDIM;
            uint32_t dstb = ((st + 1) & 1) ? cbu1 : cbu0;
#pragma unroll
            for (int it = 0; it < 8; ++it) {
                int id = tid + it * 256;
                int cc = id >> 5, kc = (id & 31) * 8;
                CP_ASYNC16(dstb + (uint32_t)(cc * ZP + kc) * 2, src + cc * CDIM + kc);
            }
            CP_COMMIT();
        }

        // ---- compute stage st on buffer st&1 ----
        uint32_t bwa = ((st & 1) ? cbu1 : cbu0) + (uint32_t)(ch * 32) * (ZP * 2) + b_lane_off;

        float4 acc[4];
#pragma unroll
        for (int nj = 0; nj < 4; ++nj) acc[nj] = make_float4(0.f, 0.f, 0.f, 0.f);

#pragma unroll 4
        for (int ks = 0; ks < 16; ++ks) {
            uint32_t kb = (uint32_t)(ks * 16 * 2);      // 16 halves = 32B
            uint32_t A[4], B0[4], B1[4];
            LDMX4(A[0], A[1], A[2], A[3], za + kb);
            LDMX4(B0[0], B0[1], B0[2], B0[3], bwa + kb);                 // codes 0-15
            LDMX4(B1[0], B1[1], B1[2], B1[3], bwa + 16u * (ZP * 2) + kb); // codes 16-31
            mma16816(acc[0], A, B0);
            mma16816(acc[1], A, B0 + 2);
            mma16816(acc[2], A, B1);
            mma16816(acc[3], A, B1 + 2);
        }

        // ---- epilogue: scores + per-thread top-5 per token slot ----
        int jbase = st * SCODES + ch * 32 + c2;
#pragma unroll
        for (int nj = 0; nj < 4; ++nj) {
            int j = jbase + nj * 8;
            float cn0 = cns[j], cn1 = cns[j + 1];
            float4 c = acc[nj];
            ins5(cn0 - 2.f * c.x, j,     bv[0], bi[0]);
            ins5(cn1 - 2.f * c.y, j + 1, bv[0], bi[0]);
            ins5(cn0 - 2.f * c.z, j,     bv[1], bi[1]);
            ins5(cn1 - 2.f * c.w, j + 1, bv[1], bi[1]);
        }

        CP_WAIT0();
        __syncthreads();
    }

    // ---- per-token screened min (8 owner threads per token) ----
    const int tok0 = tg * 16 + r, tok1 = tok0 + 8;
    atomicMin(&minkey[tok0], fenc(bv[0][0]));
    atomicMin(&minkey[tok1], fenc(bv[1][0]));
    __syncthreads();

    // ---- append margin candidates ----
#pragma unroll
    for (int s = 0; s < 2; ++s) {
        int tokl = s ? tok1 : tok0;
        float thr = fdec(minkey[tokl]) + MARGIN;
#pragma unroll
        for (int q = 0; q < 5; ++q) {
            if (bv[s][q] <= thr) {
                int pos = atomicAdd(&candcnt[tokl], 1);
                if (pos < MAXCAND) cand[tokl * MAXCAND + pos] = bi[s][q];
            }
        }
    }
    __syncthreads();

    // ---- resolve: one thread per token; bit-exact rescore when ambiguous ----
    if (tid < MT) {
        int tok = tid;
        int cnt = candcnt[tok]; if (cnt > MAXCAND) cnt = MAXCAND;
        int best = cand[tok * MAXCAND];
        if (cnt > 1) {
            const float* zp = zbase + tok;
            float zn = 0.f;
#pragma unroll 8
            for (int k = 0; k < CDIM; ++k) {
                float v = zp[(size_t)k * SP];
                zn = __fadd_rn(zn, __fmul_rn(v, v));
            }
            float bsc = 3.4e38f; best = 0x7fffffff;
            for (int q = 0; q < cnt; ++q) {
                int j = cand[tok * MAXCAND + q];
                const float* cr = cb + (size_t)j * CDIM;
                float acc = 0.f;
#pragma unroll 8
                for (int k = 0; k < CDIM; ++k)
                    acc = __fmaf_rn(zp[(size_t)k * SP], cr[k], acc);
                float sc = __fadd_rn(__fadd_rn(zn, __fmul_rn(acc, -2.f)), cns[j]);
                if (sc < bsc || (sc == bsc && j < best)) { bsc = sc; best = j; }
            }
        }
        int n = n0 + tok;
        g_idx[n] = best;
        if (oidx) oidx[n] = (float)best;
    }
}

// ---------------------------------------------------------------------------
// gather + transpose writer: 32 tokens x 256 ch, vectorized 128-bit I/O
// ---------------------------------------------------------------------------
#define WT 32
#define WP 33
__global__ __launch_bounds__(256) void write_kernel(
    const float* __restrict__ cb, const float* __restrict__ z,
    float* __restrict__ outq, float* __restrict__ outst)
{
    __shared__ float tile[CDIM * WP];
    __shared__ int   sidx[WT];

    const int tid = threadIdx.x;
    const int n0  = blockIdx.x * WT;
    const int b   = n0 / SP, s0 = n0 % SP;

    if (tid < WT) sidx[tid] = g_idx[n0 + tid];
    __syncthreads();

    const int c = tid;
#pragma unroll 8
    for (int tok = 0; tok < WT; ++tok)
        tile[c * WP + tok] = cb[(size_t)sidx[tok] * CDIM + c];
    __syncthreads();

    // phase 2: 4 consecutive tokens per thread -> LDG.128/STG.128
    const size_t base = (size_t)b * CDIM * SP + s0;
    const int tok4 = (tid & 7) * 4;
    int cc = tid >> 3;                     // 0..31, step 32, 8 iters
#pragma unroll 8
    for (int it = 0; it < 8; ++it, cc += 32) {
        size_t addr = base + (size_t)cc * SP + tok4;
        const float* tp = &tile[cc * WP + tok4];
        float4 q = make_float4(tp[0], tp[1], tp[2], tp[3]);
        *(float4*)(outq + addr) = q;
        if (outst) {
            float4 zv = *(const float4*)(z + addr);
            float4 st;
            st.x = __fadd_rn(zv.x, __fadd_rn(q.x, -zv.x));
            st.y = __fadd_rn(zv.y, __fadd_rn(q.y, -zv.y));
            st.z = __fadd_rn(zv.z, __fadd_rn(q.z, -zv.z));
            st.w = __fadd_rn(zv.w, __fadd_rn(q.w, -zv.w));
            *(float4*)(outst + addr) = st;
        }
    }
}

// ---------------------------------------------------------------------------
extern "C" void kernel_launch(void* const* d_in, const int* in_sizes, int n_in,
                              void* d_out, int out_size) {
    const float* z  = (const float*)d_in[0];
    const float* cb = (const float*)d_in[1];
    float* out = (float*)d_out;

    float* outq   = out;
    float* outst  = nullptr;
    float* outidx = nullptr;
    if (out_size >= 2 * NQ + NTOK)      { outst = out + NQ; outidx = out + 2 * (size_t)NQ; }
    else if (out_size >= 2 * NQ)        { outst = out + NQ; }
    else if (out_size >= NQ + NTOK)     { outidx = out + NQ; }

    cudaFuncSetAttribute(screen_kernel, cudaFuncAttributeMaxDynamicSharedMemorySize, SM_TOTAL);

    cnorm_kernel<<<NCODE / 256, 256>>>(cb);
    cbh_kernel<<<NCODE * CDIM / 256, 256>>>(cb);
    screen_kernel<<<NTOK / MT, 256, SM_TOTAL>>>(z, cb, outidx);
    write_kernel<<<NTOK / WT, 256>>>(cb, z, outq, outst);
}